// round 3
// baseline (speedup 1.0000x reference)
#include <cuda_runtime.h>

#define NC 16

// out[i] = center[argmin_m |x[i] - center[m]|]
// Forward value of the soft-quantizer with straight-through estimator:
// stop_gradient(W_hard - W_soft) + W_soft == W_hard up to ~1 ulp of the
// fp32 (a-b)+b round-trip (rel err ~1e-7 << 1e-3 threshold). The softmax
// branch only shapes gradients, which the forward bench never sees.

__device__ __forceinline__ float nearest_center(float v, const float* __restrict__ c) {
    float best_d = fabsf(v - c[0]);
    float best_v = c[0];
#pragma unroll
    for (int m = 1; m < NC; m++) {
        float d = fabsf(v - c[m]);
        // strict < : first index wins ties, matching jnp.argmin semantics
        bool take = d < best_d;
        best_d = take ? d : best_d;
        best_v = take ? c[m] : best_v;
    }
    return best_v;
}

__global__ __launch_bounds__(256) void quantizer_kernel(
    const float4* __restrict__ x,
    const float*  __restrict__ center,
    float4* __restrict__ out,
    int n4)
{
    float c[NC];
#pragma unroll
    for (int m = 0; m < NC; m++) c[m] = __ldg(center + m);

    int i      = blockIdx.x * blockDim.x + threadIdx.x;
    int stride = blockDim.x * gridDim.x;

    // 4x-unrolled grid-stride: 4 independent LDG.128 in flight per thread
    // before any consumer -> MLP>=4 hides DRAM latency (577/MLP model).
    for (; i + 3 * stride < n4; i += 4 * stride) {
        float4 v0 = x[i];
        float4 v1 = x[i + stride];
        float4 v2 = x[i + 2 * stride];
        float4 v3 = x[i + 3 * stride];

        float4 r0, r1, r2, r3;
        r0.x = nearest_center(v0.x, c); r0.y = nearest_center(v0.y, c);
        r0.z = nearest_center(v0.z, c); r0.w = nearest_center(v0.w, c);
        r1.x = nearest_center(v1.x, c); r1.y = nearest_center(v1.y, c);
        r1.z = nearest_center(v1.z, c); r1.w = nearest_center(v1.w, c);
        r2.x = nearest_center(v2.x, c); r2.y = nearest_center(v2.y, c);
        r2.z = nearest_center(v2.z, c); r2.w = nearest_center(v2.w, c);
        r3.x = nearest_center(v3.x, c); r3.y = nearest_center(v3.y, c);
        r3.z = nearest_center(v3.z, c); r3.w = nearest_center(v3.w, c);

        out[i]              = r0;
        out[i + stride]     = r1;
        out[i + 2 * stride] = r2;
        out[i + 3 * stride] = r3;
    }
    // Tail
    for (; i < n4; i += stride) {
        float4 v = x[i];
        float4 r;
        r.x = nearest_center(v.x, c);
        r.y = nearest_center(v.y, c);
        r.z = nearest_center(v.z, c);
        r.w = nearest_center(v.w, c);
        out[i] = r;
    }
}

extern "C" void kernel_launch(void* const* d_in, const int* in_sizes, int n_in,
                              void* d_out, int out_size)
{
    // Identify inputs by size (robust to metadata ordering):
    // x has out_size elements (16*64*128*128), center has 16.
    const float* x      = (const float*)d_in[0];
    const float* center = (const float*)d_in[1];
    if (n_in >= 2 && in_sizes[0] == NC && in_sizes[1] != NC) {
        x      = (const float*)d_in[1];
        center = (const float*)d_in[0];
    }
    float* out = (float*)d_out;

    int n  = out_size;          // 16777216 (divisible by 4)
    int n4 = n / 4;             // 4194304 float4s

    const int threads = 256;
    // 148 SMs * 16 CTAs = 2368 CTAs; each thread covers ~7 float4s
    // (one 4x batch + ~3 tail iterations).
    int blocks = 148 * 16;
    int max_blocks = (n4 + threads - 1) / threads;
    if (blocks > max_blocks) blocks = max_blocks;

    quantizer_kernel<<<blocks, threads>>>(
        (const float4*)x, center, (float4*)out, n4);
}

// round 4
// speedup vs baseline: 1.2445x; 1.2445x over previous
#include <cuda_runtime.h>

#define NC 16

// out[i] = center[argmin_m |x[i] - center[m]|]   (== forward value of the
// soft-quantizer STE: stop_gradient(W_hard - W_soft) + W_soft == W_hard,
// confirmed R3 with rel_err 8.3e-10).
//
// R3 ncu: alu pipe 79%, DRAM 24% -> ALU-bound on the 16-way distance scan.
// Replace with sorted-centers + midpoint boundaries + branchless select
// tree: 15 FSETP + 15 FSEL per element, no distance math. Sort is a
// fully-unrolled Batcher network per thread (amortized ~1 op/elem).

__device__ __forceinline__ float tree_lookup(
    float v, const float* __restrict__ sc, const float* __restrict__ bd)
{
    // sc[0..15] ascending, bd[i] = midpoint(sc[i], sc[i+1])
    float t01 = (v < bd[0])  ? sc[0]  : sc[1];
    float t23 = (v < bd[2])  ? sc[2]  : sc[3];
    float t45 = (v < bd[4])  ? sc[4]  : sc[5];
    float t67 = (v < bd[6])  ? sc[6]  : sc[7];
    float t89 = (v < bd[8])  ? sc[8]  : sc[9];
    float tab = (v < bd[10]) ? sc[10] : sc[11];
    float tcd = (v < bd[12]) ? sc[12] : sc[13];
    float tef = (v < bd[14]) ? sc[14] : sc[15];
    float q0  = (v < bd[1])  ? t01 : t23;
    float q1  = (v < bd[5])  ? t45 : t67;
    float q2  = (v < bd[9])  ? t89 : tab;
    float q3  = (v < bd[13]) ? tcd : tef;
    float h0  = (v < bd[3])  ? q0 : q1;
    float h1  = (v < bd[11]) ? q2 : q3;
    return (v < bd[7]) ? h0 : h1;
}

__global__ __launch_bounds__(256) void quantizer_kernel(
    const float4* __restrict__ x,
    const float*  __restrict__ center,
    float4* __restrict__ out,
    int n4)
{
    // Load centers and sort ascending with a Batcher odd-even mergesort
    // network (fully unrolled, branchless FMNMX pairs; all indices
    // constant-folded so sc[] stays in registers).
    float sc[NC];
#pragma unroll
    for (int m = 0; m < NC; m++) sc[m] = __ldg(center + m);

#pragma unroll
    for (int p = 1; p < NC; p *= 2) {
#pragma unroll
        for (int k = p; k >= 1; k /= 2) {
#pragma unroll
            for (int j = k % p; j + k < NC; j += 2 * k) {
#pragma unroll
                for (int i = 0; i < k; i++) {
                    int lo = j + i, hi = j + i + k;
                    if (hi < NC && (lo / (2 * p)) == (hi / (2 * p))) {
                        float a = fminf(sc[lo], sc[hi]);
                        float b = fmaxf(sc[lo], sc[hi]);
                        sc[lo] = a; sc[hi] = b;
                    }
                }
            }
        }
    }

    float bd[NC - 1];
#pragma unroll
    for (int m = 0; m < NC - 1; m++) bd[m] = 0.5f * (sc[m] + sc[m + 1]);

    int i      = blockIdx.x * blockDim.x + threadIdx.x;
    int stride = blockDim.x * gridDim.x;

    // 4x-unrolled grid-stride: 4 independent LDG.128 in flight per thread.
    for (; i + 3 * stride < n4; i += 4 * stride) {
        float4 v0 = x[i];
        float4 v1 = x[i + stride];
        float4 v2 = x[i + 2 * stride];
        float4 v3 = x[i + 3 * stride];

        float4 r0, r1, r2, r3;
        r0.x = tree_lookup(v0.x, sc, bd); r0.y = tree_lookup(v0.y, sc, bd);
        r0.z = tree_lookup(v0.z, sc, bd); r0.w = tree_lookup(v0.w, sc, bd);
        r1.x = tree_lookup(v1.x, sc, bd); r1.y = tree_lookup(v1.y, sc, bd);
        r1.z = tree_lookup(v1.z, sc, bd); r1.w = tree_lookup(v1.w, sc, bd);
        r2.x = tree_lookup(v2.x, sc, bd); r2.y = tree_lookup(v2.y, sc, bd);
        r2.z = tree_lookup(v2.z, sc, bd); r2.w = tree_lookup(v2.w, sc, bd);
        r3.x = tree_lookup(v3.x, sc, bd); r3.y = tree_lookup(v3.y, sc, bd);
        r3.z = tree_lookup(v3.z, sc, bd); r3.w = tree_lookup(v3.w, sc, bd);

        out[i]              = r0;
        out[i + stride]     = r1;
        out[i + 2 * stride] = r2;
        out[i + 3 * stride] = r3;
    }
    for (; i < n4; i += stride) {
        float4 v = x[i];
        float4 r;
        r.x = tree_lookup(v.x, sc, bd);
        r.y = tree_lookup(v.y, sc, bd);
        r.z = tree_lookup(v.z, sc, bd);
        r.w = tree_lookup(v.w, sc, bd);
        out[i] = r;
    }
}

extern "C" void kernel_launch(void* const* d_in, const int* in_sizes, int n_in,
                              void* d_out, int out_size)
{
    // Identify inputs by size (x has out_size elements, center has 16).
    const float* x      = (const float*)d_in[0];
    const float* center = (const float*)d_in[1];
    if (n_in >= 2 && in_sizes[0] == NC && in_sizes[1] != NC) {
        x      = (const float*)d_in[1];
        center = (const float*)d_in[0];
    }
    float* out = (float*)d_out;

    int n  = out_size;          // 16777216
    int n4 = n / 4;             // 4194304 float4s

    const int threads = 256;
    int blocks = 148 * 16;      // 2368 CTAs, ~7 float4s per thread
    int max_blocks = (n4 + threads - 1) / threads;
    if (blocks > max_blocks) blocks = max_blocks;

    quantizer_kernel<<<blocks, threads>>>(
        (const float4*)x, center, (float4*)out, n4);
}

// round 5
// speedup vs baseline: 1.3155x; 1.0570x over previous
#include <cuda_runtime.h>

#define NC    16
#define CELLS 2048

// out[i] = center[argmin_m |x[i] - center[m]|]  (STE forward == W_hard,
// confirmed R3/R4 with rel_err 8.3e-10).
//
// R4 ncu: alu 76.7%, DRAM 30% -> still ALU-bound on the 15-compare select
// tree (30 ops/elem). Replace comparisons with a uniform LUT:
//   prologue kernel builds 2048 cells over [bd0-pad, bd14+pad], each cell
//   stores {boundary-in-cell (or +INF), c_below, c_above} (16B).
//   main kernel: FFMA + clamp + F2I + LDS.128 + FSETP/FSEL = ~8 ops + 1 LDS.
// Cell width (~0.002) << min midpoint gap, so <=1 boundary per cell.

__device__ float4 g_lut[CELLS];
__device__ float  g_ab[2];   // a = 1/w, b = -lo/w  (cell = v*a + b)

__device__ __forceinline__ void sort_centers(float* sc) {
    // Batcher odd-even mergesort, fully unrolled (indices constant-fold).
#pragma unroll
    for (int p = 1; p < NC; p *= 2) {
#pragma unroll
        for (int k = p; k >= 1; k /= 2) {
#pragma unroll
            for (int j = k % p; j + k < NC; j += 2 * k) {
#pragma unroll
                for (int i = 0; i < k; i++) {
                    int lo = j + i, hi = j + i + k;
                    if (hi < NC && (lo / (2 * p)) == (hi / (2 * p))) {
                        float a = fminf(sc[lo], sc[hi]);
                        float b = fmaxf(sc[lo], sc[hi]);
                        sc[lo] = a; sc[hi] = b;
                    }
                }
            }
        }
    }
}

__global__ void build_lut_kernel(const float* __restrict__ center) {
    float sc[NC];
#pragma unroll
    for (int m = 0; m < NC; m++) sc[m] = center[m];
    sort_centers(sc);

    float bd[NC - 1];
#pragma unroll
    for (int m = 0; m < NC - 1; m++) bd[m] = 0.5f * (sc[m] + sc[m + 1]);

    float range = bd[NC - 2] - bd[0];
    float pad   = range * (1.0f / 256.0f) + 1e-6f;
    float lo    = bd[0] - pad;
    float w     = (range + 2.0f * pad) / (float)CELLS;

    if (threadIdx.x == 0) {
        g_ab[0] = 1.0f / w;
        g_ab[1] = -lo / w;
    }

    for (int k = threadIdx.x; k < CELLS; k += blockDim.x) {
        float s = lo + (float)k * w;
        float e = lo + (float)(k + 1) * w;
        // r0 = region index at cell start = #{ bd[j] < s }
        int r0 = 0;
#pragma unroll
        for (int j = 0; j < NC - 1; j++) r0 += (bd[j] < s) ? 1 : 0;

        float4 ent;
        if (r0 < NC - 1 && bd[r0] < e) {
            // boundary bd[r0] lies in [s, e): split cell
            ent = make_float4(bd[r0], sc[r0], sc[r0 + 1], 0.0f);
        } else {
            // boundary-free cell: constant answer
            ent = make_float4(__int_as_float(0x7F800000) /* +INF */,
                              sc[r0], sc[r0], 0.0f);
        }
        g_lut[k] = ent;
    }
}

__global__ __launch_bounds__(256) void quantizer_kernel(
    const float4* __restrict__ x,
    float4* __restrict__ out,
    int n4)
{
    __shared__ float4 lut[CELLS];
#pragma unroll 4
    for (int k = threadIdx.x; k < CELLS; k += 256) lut[k] = g_lut[k];
    const float a = g_ab[0];
    const float b = g_ab[1];
    __syncthreads();

    int i      = blockIdx.x * blockDim.x + threadIdx.x;
    int stride = blockDim.x * gridDim.x;

    auto lookup = [&](float v) -> float {
        float t = fmaf(v, a, b);
        t = fminf(fmaxf(t, 0.0f), (float)(CELLS - 1));  // safe for any v
        int k = (int)t;
        float4 e = lut[k];
        return (v < e.x) ? e.y : e.z;
    };

    // 4x-unrolled grid-stride: 4 independent LDG.128 in flight per thread.
    for (; i + 3 * stride < n4; i += 4 * stride) {
        float4 v0 = x[i];
        float4 v1 = x[i + stride];
        float4 v2 = x[i + 2 * stride];
        float4 v3 = x[i + 3 * stride];

        float4 r0, r1, r2, r3;
        r0.x = lookup(v0.x); r0.y = lookup(v0.y); r0.z = lookup(v0.z); r0.w = lookup(v0.w);
        r1.x = lookup(v1.x); r1.y = lookup(v1.y); r1.z = lookup(v1.z); r1.w = lookup(v1.w);
        r2.x = lookup(v2.x); r2.y = lookup(v2.y); r2.z = lookup(v2.z); r2.w = lookup(v2.w);
        r3.x = lookup(v3.x); r3.y = lookup(v3.y); r3.z = lookup(v3.z); r3.w = lookup(v3.w);

        out[i]              = r0;
        out[i + stride]     = r1;
        out[i + 2 * stride] = r2;
        out[i + 3 * stride] = r3;
    }
    for (; i < n4; i += stride) {
        float4 v = x[i];
        float4 r;
        r.x = lookup(v.x); r.y = lookup(v.y);
        r.z = lookup(v.z); r.w = lookup(v.w);
        out[i] = r;
    }
}

extern "C" void kernel_launch(void* const* d_in, const int* in_sizes, int n_in,
                              void* d_out, int out_size)
{
    // Identify inputs by size (x has out_size elements, center has 16).
    const float* x      = (const float*)d_in[0];
    const float* center = (const float*)d_in[1];
    if (n_in >= 2 && in_sizes[0] == NC && in_sizes[1] != NC) {
        x      = (const float*)d_in[1];
        center = (const float*)d_in[0];
    }
    float* out = (float*)d_out;

    int n  = out_size;   // 16777216
    int n4 = n / 4;      // 4194304 float4s

    build_lut_kernel<<<1, 256>>>(center);

    const int threads = 256;
    int blocks = 148 * 4;     // 592 CTAs: 4/SM, ~28 float4s per thread
    int max_blocks = (n4 + threads - 1) / threads;
    if (blocks > max_blocks) blocks = max_blocks;

    quantizer_kernel<<<blocks, threads>>>(
        (const float4*)x, (float4*)out, n4);
}

// round 6
// speedup vs baseline: 1.3177x; 1.0017x over previous
#include <cuda_runtime.h>

#define NC    16
#define CELLS 2048

// out[i] = center[argmin_m |x[i] - center[m]|]  (STE forward == W_hard,
// rel_err 8.3e-10 confirmed R3-R5).
//
// R5 ncu: L1tex 71.9%, issue 16.1%, occ 41.5% -> latency-bound on random
// LDS.128 + low occupancy. This version:
//  - 8B hot path: pairs[k]={bd_or_INF,c_lo} LDS.64; chi[k]=c_hi loaded
//    only when v>=bd (rare: boundary cells are ~1% of probability mass)
//  - LUT built in-kernel per CTA (no prologue kernel, no global LUT copy)
//  - __launch_bounds__(256,5): 24KB smem, <=51 regs -> 5 CTAs/SM (40 warps)

__device__ __forceinline__ void sort_centers(float* sc) {
    // Batcher odd-even mergesort, fully unrolled (indices constant-fold).
#pragma unroll
    for (int p = 1; p < NC; p *= 2) {
#pragma unroll
        for (int k = p; k >= 1; k /= 2) {
#pragma unroll
            for (int j = k % p; j + k < NC; j += 2 * k) {
#pragma unroll
                for (int i = 0; i < k; i++) {
                    int lo = j + i, hi = j + i + k;
                    if (hi < NC && (lo / (2 * p)) == (hi / (2 * p))) {
                        float a = fminf(sc[lo], sc[hi]);
                        float b = fmaxf(sc[lo], sc[hi]);
                        sc[lo] = a; sc[hi] = b;
                    }
                }
            }
        }
    }
}

__global__ __launch_bounds__(256, 5) void quantizer_kernel(
    const float4* __restrict__ x,
    const float*  __restrict__ center,
    float4* __restrict__ out,
    int n4)
{
    __shared__ float2 pairs[CELLS];  // {boundary-in-cell or +INF, c_below}
    __shared__ float  chi[CELLS];    // c_above (read only when v >= bd)

    // ---- per-CTA LUT build (every thread redundantly sorts; ~700 ops) ----
    float sc[NC];
#pragma unroll
    for (int m = 0; m < NC; m++) sc[m] = __ldg(center + m);
    sort_centers(sc);

    float bd[NC - 1];
#pragma unroll
    for (int m = 0; m < NC - 1; m++) bd[m] = 0.5f * (sc[m] + sc[m + 1]);

    const float range = bd[NC - 2] - bd[0];
    const float pad   = range * (1.0f / 256.0f) + 1e-6f;
    const float lo    = bd[0] - pad;
    const float w     = (range + 2.0f * pad) / (float)CELLS;
    const float a     = 1.0f / w;
    const float b     = -lo * a;
    const float INF   = __int_as_float(0x7F800000);

#pragma unroll
    for (int r = 0; r < CELLS / 256; r++) {
        int k = threadIdx.x + r * 256;
        float s = lo + (float)k * w;
        float e = s + w;
        float cl = sc[0];     // center of region at cell start
        float bb = INF;       // boundary inside [s, e), if any
        float ch = sc[0];     // center above that boundary
#pragma unroll
        for (int j = 0; j < NC - 1; j++) {
            bool below  = bd[j] < s;            // boundary before cell
            bool inside = (bd[j] < e) && !below; // boundary within cell
            cl = below  ? sc[j + 1] : cl;
            bb = inside ? bd[j]     : bb;
            ch = inside ? sc[j + 1] : ch;
        }
        pairs[k] = make_float2(bb, cl);
        chi[k]   = ch;
    }
    __syncthreads();

    // ---- streaming lookup ----
    int i      = blockIdx.x * blockDim.x + threadIdx.x;
    int stride = blockDim.x * gridDim.x;

    auto lookup = [&](float v) -> float {
        int k = __float2int_rz(fmaf(v, a, b));
        k = max(0, min(k, CELLS - 1));
        float2 p = pairs[k];
        float ans = p.y;
        if (v >= p.x) ans = chi[k];   // predicated, rare
        return ans;
    };

    // 4x-unrolled grid-stride: 4 independent LDG.128 in flight per thread.
    for (; i + 3 * stride < n4; i += 4 * stride) {
        float4 v0 = x[i];
        float4 v1 = x[i + stride];
        float4 v2 = x[i + 2 * stride];
        float4 v3 = x[i + 3 * stride];

        float4 r0, r1, r2, r3;
        r0.x = lookup(v0.x); r0.y = lookup(v0.y); r0.z = lookup(v0.z); r0.w = lookup(v0.w);
        r1.x = lookup(v1.x); r1.y = lookup(v1.y); r1.z = lookup(v1.z); r1.w = lookup(v1.w);
        r2.x = lookup(v2.x); r2.y = lookup(v2.y); r2.z = lookup(v2.z); r2.w = lookup(v2.w);
        r3.x = lookup(v3.x); r3.y = lookup(v3.y); r3.z = lookup(v3.z); r3.w = lookup(v3.w);

        out[i]              = r0;
        out[i + stride]     = r1;
        out[i + 2 * stride] = r2;
        out[i + 3 * stride] = r3;
    }
    for (; i < n4; i += stride) {
        float4 v = x[i];
        float4 r;
        r.x = lookup(v.x); r.y = lookup(v.y);
        r.z = lookup(v.z); r.w = lookup(v.w);
        out[i] = r;
    }
}

extern "C" void kernel_launch(void* const* d_in, const int* in_sizes, int n_in,
                              void* d_out, int out_size)
{
    // Identify inputs by size (x has out_size elements, center has 16).
    const float* x      = (const float*)d_in[0];
    const float* center = (const float*)d_in[1];
    if (n_in >= 2 && in_sizes[0] == NC && in_sizes[1] != NC) {
        x      = (const float*)d_in[1];
        center = (const float*)d_in[0];
    }
    float* out = (float*)d_out;

    int n  = out_size;   // 16777216
    int n4 = n / 4;      // 4194304 float4s

    const int threads = 256;
    int blocks = 148 * 5;     // 740 CTAs: 5/SM, ~22 float4s per thread
    int max_blocks = (n4 + threads - 1) / threads;
    if (blocks > max_blocks) blocks = max_blocks;

    quantizer_kernel<<<blocks, threads>>>(
        (const float4*)x, center, (float4*)out, n4);
}

// round 7
// speedup vs baseline: 1.4635x; 1.1106x over previous
#include <cuda_runtime.h>

#define NC 16

// out[i] = center[argmin_m |x[i] - center[m]|]  (STE forward == W_hard,
// rel_err 8.3e-10 confirmed R3-R6).
//
// R4 evidence: FSETP+FSEL both issue on the ALU pipe -> 30 alu-ops/elem,
// pipe-bound at ~37us. R5/R6: smem LUT trades that for L1tex latency,
// ~31-37us. This version balances the pipes instead:
//   nearest(v) = c0 + sum_j d_j * [v >= bd_j],  d_j = c[j+1]-c[j] > 0
// emitted as FSETP (alu) + predicated FADD (fma) via inline PTX:
// 15 ops/pipe/elem -> issue- and pipe-bound together at ~14us, under the
// ~19-20us DRAM floor. No smem, no LUT, no barrier.

__device__ __forceinline__ void sort_centers(float* sc) {
    // Batcher odd-even mergesort, fully unrolled (indices constant-fold).
#pragma unroll
    for (int p = 1; p < NC; p *= 2) {
#pragma unroll
        for (int k = p; k >= 1; k /= 2) {
#pragma unroll
            for (int j = k % p; j + k < NC; j += 2 * k) {
#pragma unroll
                for (int i = 0; i < k; i++) {
                    int lo = j + i, hi = j + i + k;
                    if (hi < NC && (lo / (2 * p)) == (hi / (2 * p))) {
                        float a = fminf(sc[lo], sc[hi]);
                        float b = fmaxf(sc[lo], sc[hi]);
                        sc[lo] = a; sc[hi] = b;
                    }
                }
            }
        }
    }
}

__global__ __launch_bounds__(256) void quantizer_kernel(
    const float4* __restrict__ x,
    const float*  __restrict__ center,
    float4* __restrict__ out,
    int n4)
{
    // ~160 setup ops per thread, amortized over ~70 elements.
    float sc[NC];
#pragma unroll
    for (int m = 0; m < NC; m++) sc[m] = __ldg(center + m);
    sort_centers(sc);

    float bd[NC - 1], dl[NC - 1];
#pragma unroll
    for (int m = 0; m < NC - 1; m++) {
        bd[m] = 0.5f * (sc[m] + sc[m + 1]);
        dl[m] = sc[m + 1] - sc[m];          // > 0 (sorted)
    }
    const float c0 = sc[0];

    auto lookup = [&](float v) -> float {
        float a0 = c0, a1 = 0.0f;   // two accumulators: halve FADD chain
#pragma unroll
        for (int j = 0; j < NC - 1; j++) {
            if (j & 1) {
                asm("{ .reg .pred p; setp.ge.f32 p, %1, %2; @p add.f32 %0, %0, %3; }"
                    : "+f"(a1) : "f"(v), "f"(bd[j]), "f"(dl[j]));
            } else {
                asm("{ .reg .pred p; setp.ge.f32 p, %1, %2; @p add.f32 %0, %0, %3; }"
                    : "+f"(a0) : "f"(v), "f"(bd[j]), "f"(dl[j]));
            }
        }
        return a0 + a1;
    };

    int i      = blockIdx.x * blockDim.x + threadIdx.x;
    int stride = blockDim.x * gridDim.x;

    // 2x-unrolled grid-stride: 2 independent LDG.128 per thread in flight;
    // occupancy (~48 warps/SM) supplies the rest of the MLP.
    for (; i + stride < n4; i += 2 * stride) {
        float4 v0 = x[i];
        float4 v1 = x[i + stride];

        float4 r0, r1;
        r0.x = lookup(v0.x); r0.y = lookup(v0.y);
        r0.z = lookup(v0.z); r0.w = lookup(v0.w);
        r1.x = lookup(v1.x); r1.y = lookup(v1.y);
        r1.z = lookup(v1.z); r1.w = lookup(v1.w);

        out[i]          = r0;
        out[i + stride] = r1;
    }
    for (; i < n4; i += stride) {
        float4 v = x[i];
        float4 r;
        r.x = lookup(v.x); r.y = lookup(v.y);
        r.z = lookup(v.z); r.w = lookup(v.w);
        out[i] = r;
    }
}

extern "C" void kernel_launch(void* const* d_in, const int* in_sizes, int n_in,
                              void* d_out, int out_size)
{
    // Identify inputs by size (x has out_size elements, center has 16).
    const float* x      = (const float*)d_in[0];
    const float* center = (const float*)d_in[1];
    if (n_in >= 2 && in_sizes[0] == NC && in_sizes[1] != NC) {
        x      = (const float*)d_in[1];
        center = (const float*)d_in[0];
    }
    float* out = (float*)d_out;

    int n  = out_size;   // 16777216
    int n4 = n / 4;      // 4194304 float4s

    const int threads = 256;
    int blocks = 148 * 6;     // 888 CTAs, ~18 float4s per thread
    int max_blocks = (n4 + threads - 1) / threads;
    if (blocks > max_blocks) blocks = max_blocks;

    quantizer_kernel<<<blocks, threads>>>(
        (const float4*)x, center, (float4*)out, n4);
}

// round 16
// speedup vs baseline: 1.5467x; 1.0569x over previous
#include <cuda_runtime.h>

#define NC    16
#define CELLS 2048

// out[i] = center[argmin_m |x[i] - center[m]|]  (STE forward == W_hard).
//
// R7 evidence: compare-based select floors at ~30 ops/elem (33.3us, issue
// 62%). LUT path is the only structure far below the ~19-20us DRAM floor.
// R5/R6's LUT losses are each fixed here:
//   - 8B smem entries {bd_or_INF, c_lo} (LDS.64); c_hi via rare @p LDG
//   - LUT built once by a 1-CTA prologue; main CTAs copy 16KB (4 uint4/thr)
//   - 16KB smem + launch_bounds(256,6) -> 48 warps/SM

__device__ float2 g_pairs[CELLS];   // {boundary-in-cell or +INF, c_below}
__device__ float  g_chi[CELLS];     // c_above (read only when v >= bd)
__device__ float2 g_ab;             // cell = v*x + y

__device__ __forceinline__ void sort_centers(float* sc) {
    // Batcher odd-even mergesort, fully unrolled (indices constant-fold).
#pragma unroll
    for (int p = 1; p < NC; p *= 2) {
#pragma unroll
        for (int k = p; k >= 1; k /= 2) {
#pragma unroll
            for (int j = k % p; j + k < NC; j += 2 * k) {
#pragma unroll
                for (int i = 0; i < k; i++) {
                    int lo = j + i, hi = j + i + k;
                    if (hi < NC && (lo / (2 * p)) == (hi / (2 * p))) {
                        float a = fminf(sc[lo], sc[hi]);
                        float b = fmaxf(sc[lo], sc[hi]);
                        sc[lo] = a; sc[hi] = b;
                    }
                }
            }
        }
    }
}

__global__ void build_lut_kernel(const float* __restrict__ center) {
    float sc[NC];
#pragma unroll
    for (int m = 0; m < NC; m++) sc[m] = center[m];
    sort_centers(sc);

    float bd[NC - 1];
#pragma unroll
    for (int m = 0; m < NC - 1; m++) bd[m] = 0.5f * (sc[m] + sc[m + 1]);

    const float range = bd[NC - 2] - bd[0];
    const float pad   = range * (1.0f / 256.0f) + 1e-6f;
    const float lo    = bd[0] - pad;
    const float w     = (range + 2.0f * pad) / (float)CELLS;
    const float INF   = __int_as_float(0x7F800000);

    if (threadIdx.x == 0) g_ab = make_float2(1.0f / w, -lo / w);

    for (int k = threadIdx.x; k < CELLS; k += blockDim.x) {
        float s = lo + (float)k * w;
        float e = s + w;
        float cl = sc[0], bb = INF, ch = sc[0];
#pragma unroll
        for (int j = 0; j < NC - 1; j++) {
            bool below  = bd[j] < s;
            bool inside = (bd[j] < e) && !below;
            cl = below  ? sc[j + 1] : cl;
            bb = inside ? bd[j]     : bb;
            ch = inside ? sc[j + 1] : ch;
        }
        g_pairs[k] = make_float2(bb, cl);
        g_chi[k]   = ch;
    }
}

__global__ __launch_bounds__(256, 6) void quantizer_kernel(
    const float4* __restrict__ x,
    float4* __restrict__ out,
    int n4)
{
    __shared__ float2 s_pairs[CELLS];   // 16 KB

    // Copy LUT: 1024 uint4, 4 per thread.
    {
        const uint4* src = (const uint4*)g_pairs;
        uint4* dst = (uint4*)s_pairs;
#pragma unroll
        for (int r = 0; r < CELLS / 2 / 256; r++)
            dst[threadIdx.x + r * 256] = src[threadIdx.x + r * 256];
    }
    const float2 ab = g_ab;
    __syncthreads();

    const float kmaxf = (float)(CELLS - 1);

    auto lookup = [&](float v) -> float {
        // float-side clamp folds into FMNMX pair; single F2I after.
        float t = fminf(fmaxf(fmaf(v, ab.x, ab.y), 0.0f), kmaxf);
        int k = __float2int_rz(t);
        float2 p = s_pairs[k];
        float ans = p.y;
        if (v >= p.x) ans = __ldg(&g_chi[k]);   // ~1% of lanes, L1-hot
        return ans;
    };

    int i      = blockIdx.x * blockDim.x + threadIdx.x;
    int stride = blockDim.x * gridDim.x;

    // 4x-unrolled grid-stride: 4 independent LDG.128 in flight per thread.
    for (; i + 3 * stride < n4; i += 4 * stride) {
        float4 v0 = x[i];
        float4 v1 = x[i + stride];
        float4 v2 = x[i + 2 * stride];
        float4 v3 = x[i + 3 * stride];

        float4 r0, r1, r2, r3;
        r0.x = lookup(v0.x); r0.y = lookup(v0.y); r0.z = lookup(v0.z); r0.w = lookup(v0.w);
        r1.x = lookup(v1.x); r1.y = lookup(v1.y); r1.z = lookup(v1.z); r1.w = lookup(v1.w);
        r2.x = lookup(v2.x); r2.y = lookup(v2.y); r2.z = lookup(v2.z); r2.w = lookup(v2.w);
        r3.x = lookup(v3.x); r3.y = lookup(v3.y); r3.z = lookup(v3.z); r3.w = lookup(v3.w);

        out[i]              = r0;
        out[i + stride]     = r1;
        out[i + 2 * stride] = r2;
        out[i + 3 * stride] = r3;
    }
    for (; i < n4; i += stride) {
        float4 v = x[i];
        float4 r;
        r.x = lookup(v.x); r.y = lookup(v.y);
        r.z = lookup(v.z); r.w = lookup(v.w);
        out[i] = r;
    }
}

extern "C" void kernel_launch(void* const* d_in, const int* in_sizes, int n_in,
                              void* d_out, int out_size)
{
    // Identify inputs by size (x has out_size elements, center has 16).
    const float* x      = (const float*)d_in[0];
    const float* center = (const float*)d_in[1];
    if (n_in >= 2 && in_sizes[0] == NC && in_sizes[1] != NC) {
        x      = (const float*)d_in[1];
        center = (const float*)d_in[0];
    }
    float* out = (float*)d_out;

    int n  = out_size;   // 16777216
    int n4 = n / 4;      // 4194304 float4s

    build_lut_kernel<<<1, 256>>>(center);

    const int threads = 256;
    int blocks = 148 * 6;     // 888 CTAs, 6/SM, ~18 float4s per thread
    int max_blocks = (n4 + threads - 1) / threads;
    if (blocks > max_blocks) blocks = max_blocks;

    quantizer_kernel<<<blocks, threads>>>(
        (const float4*)x, (float4*)out, n4);
}

// round 17
// speedup vs baseline: 1.5610x; 1.0092x over previous
#include <cuda_runtime.h>

#define NC    16
#define CELLS 2048

// out[i] = center[argmin_m |x[i] - center[m]|]  (STE forward == W_hard,
// rel_err 8.3e-10 confirmed).
//
// R16 ncu: L1tex 64%, issue 26.5%, DRAM 40% -> latency-bound; the per-elem
// predicated @p LDG(g_chi) serializes every lookup on an LDG scoreboard.
// Fix: fully branchless hot path with two INDEPENDENT unconditional smem
// reads (LDS.64 pairs[k] + LDS.32 chi[k], same k -> overlapped latency)
// and one FSEL. No LDG, no branch in the loop.

__device__ float2 g_pairs[CELLS];   // {boundary-in-cell or +INF, c_below}
__device__ float  g_chi[CELLS];     // c_above
__device__ float2 g_ab;             // cell = v*x + y

__device__ __forceinline__ void sort_centers(float* sc) {
    // Batcher odd-even mergesort, fully unrolled (indices constant-fold).
#pragma unroll
    for (int p = 1; p < NC; p *= 2) {
#pragma unroll
        for (int k = p; k >= 1; k /= 2) {
#pragma unroll
            for (int j = k % p; j + k < NC; j += 2 * k) {
#pragma unroll
                for (int i = 0; i < k; i++) {
                    int lo = j + i, hi = j + i + k;
                    if (hi < NC && (lo / (2 * p)) == (hi / (2 * p))) {
                        float a = fminf(sc[lo], sc[hi]);
                        float b = fmaxf(sc[lo], sc[hi]);
                        sc[lo] = a; sc[hi] = b;
                    }
                }
            }
        }
    }
}

__global__ void build_lut_kernel(const float* __restrict__ center) {
    float sc[NC];
#pragma unroll
    for (int m = 0; m < NC; m++) sc[m] = center[m];
    sort_centers(sc);

    float bd[NC - 1];
#pragma unroll
    for (int m = 0; m < NC - 1; m++) bd[m] = 0.5f * (sc[m] + sc[m + 1]);

    const float range = bd[NC - 2] - bd[0];
    const float pad   = range * (1.0f / 256.0f) + 1e-6f;
    const float lo    = bd[0] - pad;
    const float w     = (range + 2.0f * pad) / (float)CELLS;
    const float INF   = __int_as_float(0x7F800000);

    if (threadIdx.x == 0) g_ab = make_float2(1.0f / w, -lo / w);

    for (int k = threadIdx.x; k < CELLS; k += blockDim.x) {
        float s = lo + (float)k * w;
        float e = s + w;
        float cl = sc[0], bb = INF, ch = sc[0];
#pragma unroll
        for (int j = 0; j < NC - 1; j++) {
            bool below  = bd[j] < s;
            bool inside = (bd[j] < e) && !below;
            cl = below  ? sc[j + 1] : cl;
            bb = inside ? bd[j]     : bb;
            ch = inside ? sc[j + 1] : ch;
        }
        g_pairs[k] = make_float2(bb, cl);
        g_chi[k]   = ch;
    }
}

__global__ __launch_bounds__(256, 6) void quantizer_kernel(
    const float4* __restrict__ x,
    float4* __restrict__ out,
    int n4)
{
    __shared__ float2 s_pairs[CELLS];   // 16 KB
    __shared__ float  s_chi[CELLS];     //  8 KB

    // Copy LUTs: pairs as 1024 uint4 (4/thread), chi as 512 uint4 (2/thread).
    {
        const uint4* src = (const uint4*)g_pairs;
        uint4* dst = (uint4*)s_pairs;
#pragma unroll
        for (int r = 0; r < CELLS / 2 / 256; r++)
            dst[threadIdx.x + r * 256] = src[threadIdx.x + r * 256];
        const uint4* src2 = (const uint4*)g_chi;
        uint4* dst2 = (uint4*)s_chi;
#pragma unroll
        for (int r = 0; r < CELLS / 4 / 256; r++)
            dst2[threadIdx.x + r * 256] = src2[threadIdx.x + r * 256];
    }
    const float2 ab = g_ab;
    __syncthreads();

    const float kmaxf = (float)(CELLS - 1);

    auto lookup = [&](float v) -> float {
        float t = fminf(fmaxf(fmaf(v, ab.x, ab.y), 0.0f), kmaxf);
        int k = __float2int_rz(t);
        float2 p = s_pairs[k];   // LDS.64  (independent of s_chi read)
        float  h = s_chi[k];     // LDS.32  (issues immediately after)
        return (v < p.x) ? p.y : h;   // FSETP + FSEL, branchless
    };

    int i      = blockIdx.x * blockDim.x + threadIdx.x;
    int stride = blockDim.x * gridDim.x;

    // 4x-unrolled grid-stride: 4 independent LDG.128 in flight per thread.
    for (; i + 3 * stride < n4; i += 4 * stride) {
        float4 v0 = x[i];
        float4 v1 = x[i + stride];
        float4 v2 = x[i + 2 * stride];
        float4 v3 = x[i + 3 * stride];

        float4 r0, r1, r2, r3;
        r0.x = lookup(v0.x); r0.y = lookup(v0.y); r0.z = lookup(v0.z); r0.w = lookup(v0.w);
        r1.x = lookup(v1.x); r1.y = lookup(v1.y); r1.z = lookup(v1.z); r1.w = lookup(v1.w);
        r2.x = lookup(v2.x); r2.y = lookup(v2.y); r2.z = lookup(v2.z); r2.w = lookup(v2.w);
        r3.x = lookup(v3.x); r3.y = lookup(v3.y); r3.z = lookup(v3.z); r3.w = lookup(v3.w);

        out[i]              = r0;
        out[i + stride]     = r1;
        out[i + 2 * stride] = r2;
        out[i + 3 * stride] = r3;
    }
    for (; i < n4; i += stride) {
        float4 v = x[i];
        float4 r;
        r.x = lookup(v.x); r.y = lookup(v.y);
        r.z = lookup(v.z); r.w = lookup(v.w);
        out[i] = r;
    }
}

extern "C" void kernel_launch(void* const* d_in, const int* in_sizes, int n_in,
                              void* d_out, int out_size)
{
    // Identify inputs by size (x has out_size elements, center has 16).
    const float* x      = (const float*)d_in[0];
    const float* center = (const float*)d_in[1];
    if (n_in >= 2 && in_sizes[0] == NC && in_sizes[1] != NC) {
        x      = (const float*)d_in[1];
        center = (const float*)d_in[0];
    }
    float* out = (float*)d_out;

    int n  = out_size;   // 16777216
    int n4 = n / 4;      // 4194304 float4s

    build_lut_kernel<<<1, 256>>>(center);

    const int threads = 256;
    int blocks = 148 * 6;     // 888 CTAs, 6/SM, ~18 float4s per thread
    int max_blocks = (n4 + threads - 1) / threads;
    if (blocks > max_blocks) blocks = max_blocks;

    quantizer_kernel<<<blocks, threads>>>(
        (const float4*)x, (float4*)out, n4);
}